// round 8
// baseline (speedup 1.0000x reference)
#include <cuda_runtime.h>
#include <cuda_bf16.h>

// MultiHeadSpMM: out[r, h*D+d] = sum_{e: row[e]==r} attention[e,h] * h[col[e],h,d]
// N=100000, E=1600000, H=4, D=8 (H*D == 32). row[] is sorted.
//
// R8: block-staged design.
//   - Block owns 8 consecutive rows; its edge range is contiguous in col/att.
//   - Stage (col[e]*128, att[e][h]) int2 pairs for the block's edges into smem
//     (coalesced, clamp applied at staging).
//   - Compute: warp w = row Rbase+w, lane = feature 0..31. Per edge:
//     1 broadcast LDS.64 + 1 LDG.32 of hfeat row (32 consecutive floats =
//     exactly one 128B line = 1 L1 wavefront) + 1 FMA. Quad-unrolled.

#define MAX_NODES (1 << 21)
#define ROWS_PER_BLOCK 8
#define CHUNK 512   // edges staged per block iteration (16KB smem)

__device__ int g_row_ptr[MAX_NODES + 1];

__global__ void build_row_ptr_kernel(const int* __restrict__ row, int E, int N) {
    int e = blockIdx.x * blockDim.x + threadIdx.x;
    if (e >= E) return;
    int r = row[e];
    if (r < 0) r = 0;
    if (r >= N) r = N - 1;
    int prev;
    if (e == 0) {
        prev = -1;
    } else {
        prev = row[e - 1];
        if (prev < 0) prev = 0;
        if (prev >= N) prev = N - 1;
    }
    for (int i = prev + 1; i <= r; ++i) g_row_ptr[i] = e;
    if (e == E - 1) {
        for (int i = r + 1; i <= N; ++i) g_row_ptr[i] = E;
    }
}

__global__ __launch_bounds__(256) void spmm_staged_kernel(
    const int* __restrict__ col,
    const float* __restrict__ att,   // (E, 4)
    const float* __restrict__ hfeat, // (N, 32)
    float* __restrict__ out,         // (N, 32)
    int N)
{
    __shared__ int2 s_pairs[CHUNK * 4];  // (col_byte_off, att_bits) per (edge, head)

    const int tid  = threadIdx.x;
    const int warp = tid >> 5;
    const int lane = tid & 31;
    const int hd   = lane >> 3;

    const int Rbase = blockIdx.x * ROWS_PER_BLOCK;
    const int r = Rbase + warp;
    const bool row_ok = (r < N);

    const int blk_last = min(Rbase + ROWS_PER_BLOCK, N);
    const int blk_beg = g_row_ptr[Rbase];
    const int blk_end = g_row_ptr[blk_last];

    int beg = 0, end = 0;
    if (row_ok) {
        beg = g_row_ptr[r];
        end = g_row_ptr[r + 1];
    }

    const char* hbase = (const char*)hfeat + lane * 4;
    const int nmax = N - 1;
    float acc = 0.0f;

    for (int cb = blk_beg; cb < blk_end; cb += CHUNK) {
        const int n = min(CHUNK, blk_end - cb);

        // Stage n edges * 4 heads. Coalesced LDG; clamp col here, not in hot loop.
        for (int p = tid; p < n * 4; p += 256) {
            int e = cb + (p >> 2);
            int h = p & 3;
            int c = __ldg(&col[e]);
            c = min(max(c, 0), nmax);
            float a = __ldg(&att[e * 4 + h]);
            s_pairs[p] = make_int2(c * 128, __float_as_int(a));
        }
        __syncthreads();

        // This warp's slice of the chunk (relative indices).
        int lo = max(beg, cb) - cb;
        int hi = min(end, cb + n) - cb;   // row_ok=false => hi <= 0, loops skip

        int j = lo;
        for (; j + 3 < hi; j += 4) {
            int2 p0 = s_pairs[((j + 0) << 2) + hd];
            int2 p1 = s_pairs[((j + 1) << 2) + hd];
            int2 p2 = s_pairs[((j + 2) << 2) + hd];
            int2 p3 = s_pairs[((j + 3) << 2) + hd];
            float v0 = __ldg((const float*)(hbase + p0.x));
            float v1 = __ldg((const float*)(hbase + p1.x));
            float v2 = __ldg((const float*)(hbase + p2.x));
            float v3 = __ldg((const float*)(hbase + p3.x));
            acc = fmaf(__int_as_float(p0.y), v0, acc);
            acc = fmaf(__int_as_float(p1.y), v1, acc);
            acc = fmaf(__int_as_float(p2.y), v2, acc);
            acc = fmaf(__int_as_float(p3.y), v3, acc);
        }
        for (; j < hi; ++j) {
            int2 p = s_pairs[(j << 2) + hd];
            acc = fmaf(__int_as_float(p.y), __ldg((const float*)(hbase + p.x)), acc);
        }
        __syncthreads();
    }

    if (row_ok) {
        out[r * 32 + lane] = acc;   // 128B coalesced per warp; zeros for empty rows
    }
}

extern "C" void kernel_launch(void* const* d_in, const int* in_sizes, int n_in,
                              void* d_out, int out_size) {
    const int*   row  = (const int*)  d_in[0];
    const int*   col  = (const int*)  d_in[1];
    const float* att  = (const float*)d_in[2];
    const float* hft  = (const float*)d_in[3];
    float*       out  = (float*)      d_out;

    int E = in_sizes[0];
    int N = in_sizes[3] / 32;  // h is (N, 4, 8)

    {
        int threads = 256;
        int blocks = (E + threads - 1) / threads;
        build_row_ptr_kernel<<<blocks, threads>>>(row, E, N);
    }
    {
        int threads = 256;   // 8 warps = 8 rows per block
        int blocks = (N + ROWS_PER_BLOCK - 1) / ROWS_PER_BLOCK;
        spmm_staged_kernel<<<blocks, threads>>>(col, att, hft, out, N);
    }
}